// round 12
// baseline (speedup 1.0000x reference)
#include <cuda_runtime.h>
#include <stdint.h>
#include <math.h>

#define NN 50000
#define EE 800000
#define DIN 500
#define HH 256
#define CC 7

__device__ float g_x0[NN * HH];
__device__ float g_xa[NN * HH];
__device__ float g_xb[NN * HH];
__device__ float g_al[2][NN];
__device__ float g_ar[2][NN];
__device__ float g_Wt[DIN * HH];

__device__ int g_deg[NN];
__device__ int g_tmp[NN];
__device__ int g_bsum[64];
__device__ int g_rowptr[NN + 1];
__device__ int g_cursor[NN];
__device__ int g_csr_src[EE];

__device__ __forceinline__ float warp_sum(float v) {
#pragma unroll
    for (int o = 16; o; o >>= 1) v += __shfl_xor_sync(0xffffffffu, v, o);
    return v;
}

__device__ __forceinline__ float dot4(float4 a, float4 b) {
    return a.x * b.x + a.y * b.y + a.z * b.z + a.w * b.w;
}

__device__ __forceinline__ float2 u2f2(unsigned long long v) {
    return make_float2(__uint_as_float((unsigned)v),
                       __uint_as_float((unsigned)(v >> 32)));
}

__device__ __forceinline__ void cp16(void* s, const void* g) {
    unsigned a = (unsigned)__cvta_generic_to_shared(s);
    asm volatile("cp.async.cg.shared.global [%0], [%1], 16;" :: "r"(a), "l"(g));
}

// ---------------- W_init transpose ----------------
__global__ void k_transpose(const float* __restrict__ W) {
    int i = blockIdx.x * blockDim.x + threadIdx.x;
    if (i < DIN * HH) {
        int k = i / HH, h = i % HH;
        g_Wt[i] = W[h * DIN + k];
    }
}

// ---------------- SGEMM: FFMA2 + cp.async double buffer ----------------
__global__ __launch_bounds__(256) void k_gemm(const float* __restrict__ A,
                                              const float* __restrict__ bias) {
    // A tile in natural [row][k] layout (cp.async friendly); B in [k][col]
    __shared__ __align__(16) float As2[2][128][8];
    __shared__ __align__(16) float Bs[2][8][128];
    int tid = threadIdx.x;
    int ty = tid >> 4, tx = tid & 15;
    int bm = blockIdx.x * 128, bn = blockIdx.y * 128;
    unsigned long long acc2[8][4];
#pragma unroll
    for (int i = 0; i < 8; i++)
#pragma unroll
        for (int j = 0; j < 4; j++) acc2[i][j] = 0ull;

    int aRow = tid >> 1, aK4 = (tid & 1) * 4;
    int bK = tid >> 5, bH = (tid & 31) * 4;
    int am = bm + aRow;

    const int NKT = (DIN + 7) / 8;  // 63

    auto copy_tile = [&](int kt, int b) {
        int k0 = kt * 8 + aK4;
        float* adst = &As2[b][aRow][aK4];
        if (am < NN && k0 < DIN)
            cp16(adst, A + (size_t)am * DIN + k0);
        else
            *(float4*)adst = make_float4(0.f, 0.f, 0.f, 0.f);
        int kb = kt * 8 + bK;
        float* bdst = &Bs[b][bK][bH];
        if (kb < DIN)
            cp16(bdst, g_Wt + (size_t)kb * HH + bn + bH);
        else
            *(float4*)bdst = make_float4(0.f, 0.f, 0.f, 0.f);
    };

    copy_tile(0, 0);
    asm volatile("cp.async.commit_group;");

    for (int kt = 0; kt < NKT; kt++) {
        int cur = kt & 1;
        if (kt + 1 < NKT) copy_tile(kt + 1, 1 - cur);
        asm volatile("cp.async.commit_group;");
        asm volatile("cp.async.wait_group 1;");
        __syncthreads();

#pragma unroll
        for (int kk = 0; kk < 8; kk++) {
            float a[8];
#pragma unroll
            for (int i = 0; i < 4; i++) {
                a[i] = As2[cur][ty * 4 + i][kk];
                a[i + 4] = As2[cur][64 + ty * 4 + i][kk];
            }
            ulonglong2 bq0 = *(const ulonglong2*)&Bs[cur][kk][tx * 4];
            ulonglong2 bq1 = *(const ulonglong2*)&Bs[cur][kk][64 + tx * 4];
            unsigned long long b2[4] = {bq0.x, bq0.y, bq1.x, bq1.y};
            unsigned long long ad[8];
#pragma unroll
            for (int i = 0; i < 8; i++)
                asm("mov.b64 %0, {%1, %1};"
                    : "=l"(ad[i]) : "r"(__float_as_uint(a[i])));
#pragma unroll
            for (int i = 0; i < 8; i++)
#pragma unroll
                for (int j = 0; j < 4; j++)
                    asm("fma.rn.f32x2 %0, %1, %2, %0;"
                        : "+l"(acc2[i][j]) : "l"(ad[i]), "l"(b2[j]));
        }
        __syncthreads();
    }

    float4 bias0 = *(const float4*)(bias + bn + tx * 4);
    float4 bias1 = *(const float4*)(bias + bn + 64 + tx * 4);
#pragma unroll
    for (int i = 0; i < 8; i++) {
        int m = bm + (i < 4 ? ty * 4 + i : 64 + ty * 4 + (i - 4));
        if (m >= NN) continue;
        float2 p0 = u2f2(acc2[i][0]), p1 = u2f2(acc2[i][1]);
        float2 p2 = u2f2(acc2[i][2]), p3 = u2f2(acc2[i][3]);
        float4 o0 = make_float4(p0.x + bias0.x, p0.y + bias0.y,
                                p1.x + bias0.z, p1.y + bias0.w);
        float4 o1 = make_float4(p2.x + bias1.x, p2.y + bias1.y,
                                p3.x + bias1.z, p3.y + bias1.w);
        *(float4*)(g_x0 + (size_t)m * HH + bn + tx * 4) = o0;
        *(float4*)(g_x0 + (size_t)m * HH + bn + 64 + tx * 4) = o1;
    }
}

// ---------------- CSR build ----------------
__global__ void k_zero_deg() {
    int i = blockIdx.x * blockDim.x + threadIdx.x;
    if (i < NN) g_deg[i] = 0;
}
__global__ void k_hist(const int* __restrict__ dst) {
    int e = blockIdx.x * blockDim.x + threadIdx.x;
    if (e < EE) atomicAdd(&g_deg[dst[e]], 1);
}
__global__ __launch_bounds__(1024) void k_scan_local() {
    __shared__ int sh[1024];
    int i = blockIdx.x * 1024 + threadIdx.x;
    int v = (i < NN) ? g_deg[i] : 0;
    sh[threadIdx.x] = v;
    __syncthreads();
#pragma unroll
    for (int o = 1; o < 1024; o <<= 1) {
        int t = (threadIdx.x >= o) ? sh[threadIdx.x - o] : 0;
        __syncthreads();
        sh[threadIdx.x] += t;
        __syncthreads();
    }
    if (i < NN) g_tmp[i] = sh[threadIdx.x];
    if (threadIdx.x == 1023) g_bsum[blockIdx.x] = sh[1023];
}
__global__ void k_scan_bsum(int nb) {
    if (threadIdx.x == 0) {
        int s = 0;
        for (int b = 0; b < nb; b++) { s += g_bsum[b]; g_bsum[b] = s; }
    }
}
__global__ void k_scan_add() {
    int i = blockIdx.x * blockDim.x + threadIdx.x;
    if (i < NN) {
        int b = i >> 10;
        int incl = g_tmp[i] + (b > 0 ? g_bsum[b - 1] : 0);
        g_rowptr[i + 1] = incl;
        g_cursor[i] = incl - g_deg[i];
        if (i == 0) g_rowptr[0] = 0;
    }
}
__global__ void k_scatter(const int* __restrict__ src, const int* __restrict__ dst) {
    int e = blockIdx.x * blockDim.x + threadIdx.x;
    if (e < EE) {
        int pos = atomicAdd(&g_cursor[dst[e]], 1);
        g_csr_src[pos] = src[e];
    }
}

// ---------------- initial gates ----------------
__global__ __launch_bounds__(256) void k_prep(const float* __restrict__ attl,
                                              const float* __restrict__ attr) {
    int w = (blockIdx.x * blockDim.x + threadIdx.x) >> 5;
    if (w >= NN) return;
    int lane = threadIdx.x & 31;
    const float4* xr = (const float4*)(g_x0 + (size_t)w * HH);
    float4 v0 = xr[lane], v1 = xr[lane + 32];
    const float4* wl = (const float4*)attl;
    const float4* wr = (const float4*)attr;
    float sl = dot4(v0, wl[lane]) + dot4(v1, wl[lane + 32]);
    float sr = dot4(v0, wr[lane]) + dot4(v1, wr[lane + 32]);
    sl = warp_sum(sl);
    sr = warp_sum(sr);
    if (lane == 0) { g_al[0][w] = sl; g_ar[0][w] = sr; }
}

// ---------------- fused layer: inline gates, R3 lane mapping ----------
template <int LIDX, bool LAST>
__global__ __launch_bounds__(256) void k_layer(
    const float* __restrict__ lng, const float* __restrict__ lnb,
    const float* __restrict__ attl, const float* __restrict__ attr,
    const float* __restrict__ Wl, const float* __restrict__ bl,
    float* __restrict__ emb_out, float* __restrict__ logp_out) {
    int d = (blockIdx.x * blockDim.x + threadIdx.x) >> 5;
    if (d >= NN) return;
    int lane = threadIdx.x & 31;

    const float* xin = (LIDX == 0) ? g_x0 : ((LIDX == 2) ? g_xb : g_xa);
    float* xout = (LIDX == 1) ? g_xb : g_xa;
    constexpr int SLOT_IN = (LIDX & 1);
    constexpr int SLOT_OUT = 1 - SLOT_IN;

    const float* alv = g_al[SLOT_IN];
    float ard = g_ar[SLOT_IN][d];
    float aself = 0.5f * tanhf(alv[d] + ard);

    const float4* xd = (const float4*)(xin + (size_t)d * HH);
    float4 v0 = xd[lane], v1 = xd[lane + 32];
    float4 acc0 = make_float4(aself * v0.x, aself * v0.y, aself * v0.z, aself * v0.w);
    float4 acc1 = make_float4(aself * v1.x, aself * v1.y, aself * v1.z, aself * v1.w);

    int beg = g_rowptr[d], end = g_rowptr[d + 1];
    for (int base = beg; base < end; base += 32) {
        int idx = base + lane;
        int s = 0;
        float g = 0.f;
        if (idx < end) {
            s = g_csr_src[idx];
            g = 0.5f * tanhf(alv[s] + ard);
        }
        int cnt = min(32, end - base);
#pragma unroll 4
        for (int j = 0; j < cnt; j++) {
            int sj = __shfl_sync(0xffffffffu, s, j);
            float gj = __shfl_sync(0xffffffffu, g, j);
            const float4* xr = (const float4*)(xin + (size_t)sj * HH);
            float4 u0 = xr[lane], u1 = xr[lane + 32];
            acc0.x = fmaf(gj, u0.x, acc0.x); acc0.y = fmaf(gj, u0.y, acc0.y);
            acc0.z = fmaf(gj, u0.z, acc0.z); acc0.w = fmaf(gj, u0.w, acc0.w);
            acc1.x = fmaf(gj, u1.x, acc1.x); acc1.y = fmaf(gj, u1.y, acc1.y);
            acc1.z = fmaf(gj, u1.z, acc1.z); acc1.w = fmaf(gj, u1.w, acc1.w);
        }
    }

    const float4* x0r = (const float4*)(g_x0 + (size_t)d * HH);
    float4 z0 = x0r[lane], z1 = x0r[lane + 32];
    acc0.x = fmaf(0.1f, z0.x, acc0.x); acc0.y = fmaf(0.1f, z0.y, acc0.y);
    acc0.z = fmaf(0.1f, z0.z, acc0.z); acc0.w = fmaf(0.1f, z0.w, acc0.w);
    acc1.x = fmaf(0.1f, z1.x, acc1.x); acc1.y = fmaf(0.1f, z1.y, acc1.y);
    acc1.z = fmaf(0.1f, z1.z, acc1.z); acc1.w = fmaf(0.1f, z1.w, acc1.w);

    if (!LAST) {
        acc0.x = fmaxf(acc0.x, 0.f); acc0.y = fmaxf(acc0.y, 0.f);
        acc0.z = fmaxf(acc0.z, 0.f); acc0.w = fmaxf(acc0.w, 0.f);
        acc1.x = fmaxf(acc1.x, 0.f); acc1.y = fmaxf(acc1.y, 0.f);
        acc1.z = fmaxf(acc1.z, 0.f); acc1.w = fmaxf(acc1.w, 0.f);
        float sum = acc0.x + acc0.y + acc0.z + acc0.w + acc1.x + acc1.y + acc1.z + acc1.w;
        float sq = acc0.x * acc0.x + acc0.y * acc0.y + acc0.z * acc0.z + acc0.w * acc0.w +
                   acc1.x * acc1.x + acc1.y * acc1.y + acc1.z * acc1.z + acc1.w * acc1.w;
        sum = warp_sum(sum);
        sq = warp_sum(sq);
        float mu = sum * (1.f / HH);
        float var = sq * (1.f / HH) - mu * mu;
        float inv = rsqrtf(var + 1e-5f);
        const float4* gp = (const float4*)lng;
        const float4* bp = (const float4*)lnb;
        float4 gg0 = gp[lane], gg1 = gp[lane + 32];
        float4 bb0 = bp[lane], bb1 = bp[lane + 32];
        float4 y0 = make_float4((acc0.x - mu) * inv * gg0.x + bb0.x,
                                (acc0.y - mu) * inv * gg0.y + bb0.y,
                                (acc0.z - mu) * inv * gg0.z + bb0.z,
                                (acc0.w - mu) * inv * gg0.w + bb0.w);
        float4 y1 = make_float4((acc1.x - mu) * inv * gg1.x + bb1.x,
                                (acc1.y - mu) * inv * gg1.y + bb1.y,
                                (acc1.z - mu) * inv * gg1.z + bb1.z,
                                (acc1.w - mu) * inv * gg1.w + bb1.w);
        float4* xw = (float4*)(xout + (size_t)d * HH);
        xw[lane] = y0;
        xw[lane + 32] = y1;
        const float4* wl = (const float4*)attl;
        const float4* wr = (const float4*)attr;
        float sl = dot4(y0, wl[lane]) + dot4(y1, wl[lane + 32]);
        float sr = dot4(y0, wr[lane]) + dot4(y1, wr[lane + 32]);
        sl = warp_sum(sl);
        sr = warp_sum(sr);
        if (lane == 0) { g_al[SLOT_OUT][d] = sl; g_ar[SLOT_OUT][d] = sr; }
    } else {
        float e[CC];
#pragma unroll
        for (int c = 0; c < CC; c++) {
            const float4* wr = (const float4*)(Wl + c * HH);
            float p = dot4(acc0, wr[lane]) + dot4(acc1, wr[lane + 32]);
            e[c] = warp_sum(p);
        }
        if (lane == 0) {
            float val[CC];
            float m = -1e30f;
#pragma unroll
            for (int c = 0; c < CC; c++) {
                val[c] = e[c] + bl[c];
                m = fmaxf(m, val[c]);
            }
            float ssum = 0.f;
#pragma unroll
            for (int c = 0; c < CC; c++) ssum += expf(val[c] - m);
            float lse = m + logf(ssum);
#pragma unroll
            for (int c = 0; c < CC; c++) {
                if (emb_out) emb_out[(size_t)d * CC + c] = val[c];
                logp_out[(size_t)d * CC + c] = val[c] - lse;
            }
        }
    }
}

extern "C" void kernel_launch(void* const* d_in, const int* in_sizes, int n_in,
                              void* d_out, int out_size) {
    const float* x_in = (const float*)d_in[0];
    const int* ei     = (const int*)d_in[1];
    const float* Wi   = (const float*)d_in[2];
    const float* bi   = (const float*)d_in[3];
    const float* attl = (const float*)d_in[4];
    const float* attr = (const float*)d_in[5];
    const float* lng  = (const float*)d_in[6];
    const float* lnb  = (const float*)d_in[7];
    const float* Wl   = (const float*)d_in[8];
    const float* bl   = (const float*)d_in[9];
    float* out = (float*)d_out;

    const int* src = ei;
    const int* dst = ei + EE;

    // CSR build
    k_zero_deg<<<(NN + 255) / 256, 256>>>();
    k_hist<<<(EE + 255) / 256, 256>>>(dst);
    int nb = (NN + 1023) / 1024;
    k_scan_local<<<nb, 1024>>>();
    k_scan_bsum<<<1, 32>>>(nb);
    k_scan_add<<<(NN + 255) / 256, 256>>>();
    k_scatter<<<(EE + 255) / 256, 256>>>(src, dst);

    // init GEMM (FFMA2 + cp.async double buffer)
    k_transpose<<<(DIN * HH + 255) / 256, 256>>>(Wi);
    dim3 gg((NN + 127) / 128, HH / 128);
    k_gemm<<<gg, 256>>>(x_in, bi);

    int nodeBlocks = (NN + 7) / 8;
    k_prep<<<nodeBlocks, 256>>>(attl, attr);

    float* embp = nullptr;
    float* logp = out;
    if (out_size >= 2 * NN * CC) {
        embp = out;
        logp = out + (size_t)NN * CC;
    }

    k_layer<0, false><<<nodeBlocks, 256>>>(lng + 0 * HH, lnb + 0 * HH,
                                           attl + 1 * HH, attr + 1 * HH,
                                           nullptr, nullptr, nullptr, nullptr);
    k_layer<1, false><<<nodeBlocks, 256>>>(lng + 1 * HH, lnb + 1 * HH,
                                           attl + 2 * HH, attr + 2 * HH,
                                           nullptr, nullptr, nullptr, nullptr);
    k_layer<2, false><<<nodeBlocks, 256>>>(lng + 2 * HH, lnb + 2 * HH,
                                           attl + 3 * HH, attr + 3 * HH,
                                           nullptr, nullptr, nullptr, nullptr);
    k_layer<3, true><<<nodeBlocks, 256>>>(nullptr, nullptr, nullptr, nullptr,
                                          Wl, bl, embp, logp);
}

// round 13
// speedup vs baseline: 1.0619x; 1.0619x over previous
#include <cuda_runtime.h>
#include <stdint.h>
#include <math.h>

#define NN 50000
#define EE 800000
#define DIN 500
#define HH 256
#define CC 7

__device__ float g_x0[NN * HH];
__device__ float g_xa[NN * HH];
__device__ float g_xb[NN * HH];
__device__ float g_al[2][NN];
__device__ float g_ar[2][NN];
__device__ float g_Wt[DIN * HH];

__device__ int g_deg[NN];
__device__ int g_tmp[NN];
__device__ int g_bsum[64];
__device__ int g_rowptr[NN + 1];
__device__ int g_cursor[NN];
__device__ int g_csr_src[EE];

__device__ __forceinline__ float warp_sum(float v) {
#pragma unroll
    for (int o = 16; o; o >>= 1) v += __shfl_xor_sync(0xffffffffu, v, o);
    return v;
}

__device__ __forceinline__ float dot4(float4 a, float4 b) {
    return a.x * b.x + a.y * b.y + a.z * b.z + a.w * b.w;
}

__device__ __forceinline__ float2 u2f2(unsigned long long v) {
    return make_float2(__uint_as_float((unsigned)v),
                       __uint_as_float((unsigned)(v >> 32)));
}

// ---------------- W_init transpose ----------------
__global__ void k_transpose(const float* __restrict__ W) {
    int i = blockIdx.x * blockDim.x + threadIdx.x;
    if (i < DIN * HH) {
        int k = i / HH, h = i % HH;
        g_Wt[i] = W[h * DIN + k];
    }
}

// ---------------- SGEMM: FFMA2, BK=16, explicit register-pipelined DB ------
__global__ __launch_bounds__(256) void k_gemm(const float* __restrict__ A,
                                              const float* __restrict__ bias) {
    __shared__ __align__(16) float As[2][16][128];  // k-major (broadcast reads)
    __shared__ __align__(16) float Bs[2][16][128];
    int tid = threadIdx.x;
    int ty = tid >> 4, tx = tid & 15;
    int bm = blockIdx.x * 128, bn = blockIdx.y * 128;
    unsigned long long acc2[8][4];
#pragma unroll
    for (int i = 0; i < 8; i++)
#pragma unroll
        for (int j = 0; j < 4; j++) acc2[i][j] = 0ull;

    // A load: float4 id f in {tid, tid+256}: row = f>>2, kq = f&3 (4 k per quad)
    int aRow0 = tid >> 2, aKq0 = (tid & 3) * 4;
    int aRow1 = (tid + 256) >> 2, aKq1 = ((tid + 256) & 3) * 4;
    // B load: f in {tid, tid+256}: kRow = f>>5, col = (f&31)*4
    int bK0 = tid >> 5, bC0 = (tid & 31) * 4;
    int bK1 = (tid + 256) >> 5, bC1 = ((tid + 256) & 31) * 4;

    const int NKT = 32;  // 32 * 16 = 512 >= 500

    float4 aR0, aR1, bR0, bR1;

    auto ldg_tile = [&](int kt) {
        int k;
        aR0 = make_float4(0.f, 0.f, 0.f, 0.f);
        aR1 = make_float4(0.f, 0.f, 0.f, 0.f);
        bR0 = make_float4(0.f, 0.f, 0.f, 0.f);
        bR1 = make_float4(0.f, 0.f, 0.f, 0.f);
        k = kt * 16 + aKq0;
        if (bm + aRow0 < NN && k < DIN)
            aR0 = *(const float4*)(A + (size_t)(bm + aRow0) * DIN + k);
        k = kt * 16 + aKq1;
        if (bm + aRow1 < NN && k < DIN)
            aR1 = *(const float4*)(A + (size_t)(bm + aRow1) * DIN + k);
        k = kt * 16 + bK0;
        if (k < DIN) bR0 = *(const float4*)(g_Wt + (size_t)k * HH + bn + bC0);
        k = kt * 16 + bK1;
        if (k < DIN) bR1 = *(const float4*)(g_Wt + (size_t)k * HH + bn + bC1);
    };

    auto sts_tile = [&](int b) {
        As[b][aKq0 + 0][aRow0] = aR0.x;
        As[b][aKq0 + 1][aRow0] = aR0.y;
        As[b][aKq0 + 2][aRow0] = aR0.z;
        As[b][aKq0 + 3][aRow0] = aR0.w;
        As[b][aKq1 + 0][aRow1] = aR1.x;
        As[b][aKq1 + 1][aRow1] = aR1.y;
        As[b][aKq1 + 2][aRow1] = aR1.z;
        As[b][aKq1 + 3][aRow1] = aR1.w;
        *(float4*)&Bs[b][bK0][bC0] = bR0;
        *(float4*)&Bs[b][bK1][bC1] = bR1;
    };

    ldg_tile(0);
    sts_tile(0);
    __syncthreads();

    for (int kt = 0; kt < NKT; kt++) {
        int cur = kt & 1;
        if (kt + 1 < NKT) ldg_tile(kt + 1);  // LDG overlaps the compute below
#pragma unroll
        for (int kk = 0; kk < 16; kk++) {
            float4 a0 = *(const float4*)&As[cur][kk][ty * 4];
            float4 a1 = *(const float4*)&As[cur][kk][64 + ty * 4];
            ulonglong2 bq0 = *(const ulonglong2*)&Bs[cur][kk][tx * 4];
            ulonglong2 bq1 = *(const ulonglong2*)&Bs[cur][kk][64 + tx * 4];
            unsigned long long b2[4] = {bq0.x, bq0.y, bq1.x, bq1.y};
            float a[8] = {a0.x, a0.y, a0.z, a0.w, a1.x, a1.y, a1.z, a1.w};
            unsigned long long ad[8];
#pragma unroll
            for (int i = 0; i < 8; i++)
                asm("mov.b64 %0, {%1, %1};"
                    : "=l"(ad[i]) : "r"(__float_as_uint(a[i])));
#pragma unroll
            for (int i = 0; i < 8; i++)
#pragma unroll
                for (int j = 0; j < 4; j++)
                    asm("fma.rn.f32x2 %0, %1, %2, %0;"
                        : "+l"(acc2[i][j]) : "l"(ad[i]), "l"(b2[j]));
        }
        if (kt + 1 < NKT) {
            __syncthreads();   // everyone done reading buf cur? no—done below
            sts_tile(1 - cur);
            __syncthreads();
        }
    }

    float4 bias0 = *(const float4*)(bias + bn + tx * 4);
    float4 bias1 = *(const float4*)(bias + bn + 64 + tx * 4);
#pragma unroll
    for (int i = 0; i < 8; i++) {
        int m = bm + (i < 4 ? ty * 4 + i : 64 + ty * 4 + (i - 4));
        if (m >= NN) continue;
        float2 p0 = u2f2(acc2[i][0]), p1 = u2f2(acc2[i][1]);
        float2 p2 = u2f2(acc2[i][2]), p3 = u2f2(acc2[i][3]);
        float4 o0 = make_float4(p0.x + bias0.x, p0.y + bias0.y,
                                p1.x + bias0.z, p1.y + bias0.w);
        float4 o1 = make_float4(p2.x + bias1.x, p2.y + bias1.y,
                                p3.x + bias1.z, p3.y + bias1.w);
        *(float4*)(g_x0 + (size_t)m * HH + bn + tx * 4) = o0;
        *(float4*)(g_x0 + (size_t)m * HH + bn + 64 + tx * 4) = o1;
    }
}

// ---------------- CSR build ----------------
__global__ void k_zero_deg() {
    int i = blockIdx.x * blockDim.x + threadIdx.x;
    if (i < NN) g_deg[i] = 0;
}
__global__ void k_hist(const int* __restrict__ dst) {
    int e = blockIdx.x * blockDim.x + threadIdx.x;
    if (e < EE) atomicAdd(&g_deg[dst[e]], 1);
}
__global__ __launch_bounds__(1024) void k_scan_local() {
    __shared__ int sh[1024];
    int i = blockIdx.x * 1024 + threadIdx.x;
    int v = (i < NN) ? g_deg[i] : 0;
    sh[threadIdx.x] = v;
    __syncthreads();
#pragma unroll
    for (int o = 1; o < 1024; o <<= 1) {
        int t = (threadIdx.x >= o) ? sh[threadIdx.x - o] : 0;
        __syncthreads();
        sh[threadIdx.x] += t;
        __syncthreads();
    }
    if (i < NN) g_tmp[i] = sh[threadIdx.x];
    if (threadIdx.x == 1023) g_bsum[blockIdx.x] = sh[1023];
}
__global__ void k_scan_bsum(int nb) {
    __shared__ int sh[64];
    int i = threadIdx.x;
    sh[i] = (i < nb) ? g_bsum[i] : 0;
    __syncthreads();
#pragma unroll
    for (int o = 1; o < 64; o <<= 1) {
        int t = (i >= o) ? sh[i - o] : 0;
        __syncthreads();
        sh[i] += t;
        __syncthreads();
    }
    if (i < nb) g_bsum[i] = sh[i];
}
__global__ void k_scan_add() {
    int i = blockIdx.x * blockDim.x + threadIdx.x;
    if (i < NN) {
        int b = i >> 10;
        int incl = g_tmp[i] + (b > 0 ? g_bsum[b - 1] : 0);
        g_rowptr[i + 1] = incl;
        g_cursor[i] = incl - g_deg[i];
        if (i == 0) g_rowptr[0] = 0;
    }
}
__global__ void k_scatter(const int* __restrict__ src, const int* __restrict__ dst) {
    int e = blockIdx.x * blockDim.x + threadIdx.x;
    if (e < EE) {
        int pos = atomicAdd(&g_cursor[dst[e]], 1);
        g_csr_src[pos] = src[e];
    }
}

// ---------------- initial gates ----------------
__global__ __launch_bounds__(256) void k_prep(const float* __restrict__ attl,
                                              const float* __restrict__ attr) {
    int w = (blockIdx.x * blockDim.x + threadIdx.x) >> 5;
    if (w >= NN) return;
    int lane = threadIdx.x & 31;
    const float4* xr = (const float4*)(g_x0 + (size_t)w * HH);
    float4 v0 = xr[lane], v1 = xr[lane + 32];
    const float4* wl = (const float4*)attl;
    const float4* wr = (const float4*)attr;
    float sl = dot4(v0, wl[lane]) + dot4(v1, wl[lane + 32]);
    float sr = dot4(v0, wr[lane]) + dot4(v1, wr[lane + 32]);
    sl = warp_sum(sl);
    sr = warp_sum(sr);
    if (lane == 0) { g_al[0][w] = sl; g_ar[0][w] = sr; }
}

// ---------------- fused layer: inline gates, R3 lane mapping (R11-proven) ---
template <int LIDX, bool LAST>
__global__ __launch_bounds__(256) void k_layer(
    const float* __restrict__ lng, const float* __restrict__ lnb,
    const float* __restrict__ attl, const float* __restrict__ attr,
    const float* __restrict__ Wl, const float* __restrict__ bl,
    float* __restrict__ emb_out, float* __restrict__ logp_out) {
    int d = (blockIdx.x * blockDim.x + threadIdx.x) >> 5;
    if (d >= NN) return;
    int lane = threadIdx.x & 31;

    const float* xin = (LIDX == 0) ? g_x0 : ((LIDX == 2) ? g_xb : g_xa);
    float* xout = (LIDX == 1) ? g_xb : g_xa;
    constexpr int SLOT_IN = (LIDX & 1);
    constexpr int SLOT_OUT = 1 - SLOT_IN;

    const float* alv = g_al[SLOT_IN];
    float ard = g_ar[SLOT_IN][d];
    float aself = 0.5f * tanhf(alv[d] + ard);

    const float4* xd = (const float4*)(xin + (size_t)d * HH);
    float4 v0 = xd[lane], v1 = xd[lane + 32];
    float4 acc0 = make_float4(aself * v0.x, aself * v0.y, aself * v0.z, aself * v0.w);
    float4 acc1 = make_float4(aself * v1.x, aself * v1.y, aself * v1.z, aself * v1.w);

    int beg = g_rowptr[d], end = g_rowptr[d + 1];
    for (int base = beg; base < end; base += 32) {
        int idx = base + lane;
        int s = 0;
        float g = 0.f;
        if (idx < end) {
            s = g_csr_src[idx];
            g = 0.5f * tanhf(alv[s] + ard);
        }
        int cnt = min(32, end - base);
#pragma unroll 4
        for (int j = 0; j < cnt; j++) {
            int sj = __shfl_sync(0xffffffffu, s, j);
            float gj = __shfl_sync(0xffffffffu, g, j);
            const float4* xr = (const float4*)(xin + (size_t)sj * HH);
            float4 u0 = xr[lane], u1 = xr[lane + 32];
            acc0.x = fmaf(gj, u0.x, acc0.x); acc0.y = fmaf(gj, u0.y, acc0.y);
            acc0.z = fmaf(gj, u0.z, acc0.z); acc0.w = fmaf(gj, u0.w, acc0.w);
            acc1.x = fmaf(gj, u1.x, acc1.x); acc1.y = fmaf(gj, u1.y, acc1.y);
            acc1.z = fmaf(gj, u1.z, acc1.z); acc1.w = fmaf(gj, u1.w, acc1.w);
        }
    }

    const float4* x0r = (const float4*)(g_x0 + (size_t)d * HH);
    float4 z0 = x0r[lane], z1 = x0r[lane + 32];
    acc0.x = fmaf(0.1f, z0.x, acc0.x); acc0.y = fmaf(0.1f, z0.y, acc0.y);
    acc0.z = fmaf(0.1f, z0.z, acc0.z); acc0.w = fmaf(0.1f, z0.w, acc0.w);
    acc1.x = fmaf(0.1f, z1.x, acc1.x); acc1.y = fmaf(0.1f, z1.y, acc1.y);
    acc1.z = fmaf(0.1f, z1.z, acc1.z); acc1.w = fmaf(0.1f, z1.w, acc1.w);

    if (!LAST) {
        acc0.x = fmaxf(acc0.x, 0.f); acc0.y = fmaxf(acc0.y, 0.f);
        acc0.z = fmaxf(acc0.z, 0.f); acc0.w = fmaxf(acc0.w, 0.f);
        acc1.x = fmaxf(acc1.x, 0.f); acc1.y = fmaxf(acc1.y, 0.f);
        acc1.z = fmaxf(acc1.z, 0.f); acc1.w = fmaxf(acc1.w, 0.f);
        float sum = acc0.x + acc0.y + acc0.z + acc0.w + acc1.x + acc1.y + acc1.z + acc1.w;
        float sq = acc0.x * acc0.x + acc0.y * acc0.y + acc0.z * acc0.z + acc0.w * acc0.w +
                   acc1.x * acc1.x + acc1.y * acc1.y + acc1.z * acc1.z + acc1.w * acc1.w;
        sum = warp_sum(sum);
        sq = warp_sum(sq);
        float mu = sum * (1.f / HH);
        float var = sq * (1.f / HH) - mu * mu;
        float inv = rsqrtf(var + 1e-5f);
        const float4* gp = (const float4*)lng;
        const float4* bp = (const float4*)lnb;
        float4 gg0 = gp[lane], gg1 = gp[lane + 32];
        float4 bb0 = bp[lane], bb1 = bp[lane + 32];
        float4 y0 = make_float4((acc0.x - mu) * inv * gg0.x + bb0.x,
                                (acc0.y - mu) * inv * gg0.y + bb0.y,
                                (acc0.z - mu) * inv * gg0.z + bb0.z,
                                (acc0.w - mu) * inv * gg0.w + bb0.w);
        float4 y1 = make_float4((acc1.x - mu) * inv * gg1.x + bb1.x,
                                (acc1.y - mu) * inv * gg1.y + bb1.y,
                                (acc1.z - mu) * inv * gg1.z + bb1.z,
                                (acc1.w - mu) * inv * gg1.w + bb1.w);
        float4* xw = (float4*)(xout + (size_t)d * HH);
        xw[lane] = y0;
        xw[lane + 32] = y1;
        const float4* wl = (const float4*)attl;
        const float4* wr = (const float4*)attr;
        float sl = dot4(y0, wl[lane]) + dot4(y1, wl[lane + 32]);
        float sr = dot4(y0, wr[lane]) + dot4(y1, wr[lane + 32]);
        sl = warp_sum(sl);
        sr = warp_sum(sr);
        if (lane == 0) { g_al[SLOT_OUT][d] = sl; g_ar[SLOT_OUT][d] = sr; }
    } else {
        float e[CC];
#pragma unroll
        for (int c = 0; c < CC; c++) {
            const float4* wr = (const float4*)(Wl + c * HH);
            float p = dot4(acc0, wr[lane]) + dot4(acc1, wr[lane + 32]);
            e[c] = warp_sum(p);
        }
        if (lane == 0) {
            float val[CC];
            float m = -1e30f;
#pragma unroll
            for (int c = 0; c < CC; c++) {
                val[c] = e[c] + bl[c];
                m = fmaxf(m, val[c]);
            }
            float ssum = 0.f;
#pragma unroll
            for (int c = 0; c < CC; c++) ssum += expf(val[c] - m);
            float lse = m + logf(ssum);
#pragma unroll
            for (int c = 0; c < CC; c++) {
                if (emb_out) emb_out[(size_t)d * CC + c] = val[c];
                logp_out[(size_t)d * CC + c] = val[c] - lse;
            }
        }
    }
}

extern "C" void kernel_launch(void* const* d_in, const int* in_sizes, int n_in,
                              void* d_out, int out_size) {
    const float* x_in = (const float*)d_in[0];
    const int* ei     = (const int*)d_in[1];
    const float* Wi   = (const float*)d_in[2];
    const float* bi   = (const float*)d_in[3];
    const float* attl = (const float*)d_in[4];
    const float* attr = (const float*)d_in[5];
    const float* lng  = (const float*)d_in[6];
    const float* lnb  = (const float*)d_in[7];
    const float* Wl   = (const float*)d_in[8];
    const float* bl   = (const float*)d_in[9];
    float* out = (float*)d_out;

    const int* src = ei;
    const int* dst = ei + EE;

    // CSR build
    k_zero_deg<<<(NN + 255) / 256, 256>>>();
    k_hist<<<(EE + 255) / 256, 256>>>(dst);
    int nb = (NN + 1023) / 1024;
    k_scan_local<<<nb, 1024>>>();
    k_scan_bsum<<<1, 64>>>(nb);
    k_scan_add<<<(NN + 255) / 256, 256>>>();
    k_scatter<<<(EE + 255) / 256, 256>>>(src, dst);

    // init GEMM (FFMA2, BK=16, register-pipelined)
    k_transpose<<<(DIN * HH + 255) / 256, 256>>>(Wi);
    dim3 gg((NN + 127) / 128, HH / 128);
    k_gemm<<<gg, 256>>>(x_in, bi);

    int nodeBlocks = (NN + 7) / 8;
    k_prep<<<nodeBlocks, 256>>>(attl, attr);

    float* embp = nullptr;
    float* logp = out;
    if (out_size >= 2 * NN * CC) {
        embp = out;
        logp = out + (size_t)NN * CC;
    }

    k_layer<0, false><<<nodeBlocks, 256>>>(lng + 0 * HH, lnb + 0 * HH,
                                           attl + 1 * HH, attr + 1 * HH,
                                           nullptr, nullptr, nullptr, nullptr);
    k_layer<1, false><<<nodeBlocks, 256>>>(lng + 1 * HH, lnb + 1 * HH,
                                           attl + 2 * HH, attr + 2 * HH,
                                           nullptr, nullptr, nullptr, nullptr);
    k_layer<2, false><<<nodeBlocks, 256>>>(lng + 2 * HH, lnb + 2 * HH,
                                           attl + 3 * HH, attr + 3 * HH,
                                           nullptr, nullptr, nullptr, nullptr);
    k_layer<3, true><<<nodeBlocks, 256>>>(nullptr, nullptr, nullptr, nullptr,
                                          Wl, bl, embp, logp);
}

// round 14
// speedup vs baseline: 1.1092x; 1.0445x over previous
#include <cuda_runtime.h>
#include <stdint.h>
#include <math.h>

#define NN 50000
#define EE 800000
#define DIN 500
#define HH 256
#define CC 7

__device__ float g_x0[NN * HH];
__device__ float g_xa[NN * HH];
__device__ float g_xb[NN * HH];
__device__ float g_al[2][NN];
__device__ float g_ar[2][NN];
__device__ float g_Wt[DIN * HH];

__device__ int g_deg[NN];
__device__ int g_tmp[NN];
__device__ int g_bsum[64];
__device__ int g_rowptr[NN + 1];
__device__ int g_cursor[NN];
__device__ int g_csr_src[EE];

__device__ __forceinline__ float warp_sum(float v) {
#pragma unroll
    for (int o = 16; o; o >>= 1) v += __shfl_xor_sync(0xffffffffu, v, o);
    return v;
}

__device__ __forceinline__ float dot4(float4 a, float4 b) {
    return a.x * b.x + a.y * b.y + a.z * b.z + a.w * b.w;
}

__device__ __forceinline__ float2 u2f2(unsigned long long v) {
    return make_float2(__uint_as_float((unsigned)v),
                       __uint_as_float((unsigned)(v >> 32)));
}

// ---------------- W_init transpose ----------------
__global__ void k_transpose(const float* __restrict__ W) {
    int i = blockIdx.x * blockDim.x + threadIdx.x;
    if (i < DIN * HH) {
        int k = i / HH, h = i % HH;
        g_Wt[i] = W[h * DIN + k];
    }
}

// ---------------- SGEMM with packed fma.rn.f32x2 (R11-proven) ----------------
__global__ __launch_bounds__(256) void k_gemm(const float* __restrict__ A,
                                              const float* __restrict__ bias) {
    __shared__ __align__(16) float As[8][128];
    __shared__ __align__(16) float Bs[8][128];
    int tid = threadIdx.x;
    int ty = tid >> 4, tx = tid & 15;
    int bm = blockIdx.x * 128, bn = blockIdx.y * 128;
    unsigned long long acc2[8][4];
#pragma unroll
    for (int i = 0; i < 8; i++)
#pragma unroll
        for (int j = 0; j < 4; j++) acc2[i][j] = 0ull;

    int aRow = tid >> 1, aK4 = (tid & 1) * 4;
    int bK = tid >> 5, bH = (tid & 31) * 4;

    for (int kt = 0; kt < DIN; kt += 8) {
        float4 av = make_float4(0.f, 0.f, 0.f, 0.f);
        int m = bm + aRow;
        if (m < NN && (kt + aK4) < DIN)
            av = *(const float4*)(A + (size_t)m * DIN + kt + aK4);
        float4 bv = make_float4(0.f, 0.f, 0.f, 0.f);
        if ((kt + bK) < DIN)
            bv = *(const float4*)(g_Wt + (kt + bK) * HH + bn + bH);
        As[aK4 + 0][aRow] = av.x;
        As[aK4 + 1][aRow] = av.y;
        As[aK4 + 2][aRow] = av.z;
        As[aK4 + 3][aRow] = av.w;
        *(float4*)&Bs[bK][bH] = bv;
        __syncthreads();
#pragma unroll
        for (int kk = 0; kk < 8; kk++) {
            float4 a0 = *(const float4*)&As[kk][ty * 4];
            float4 a1 = *(const float4*)&As[kk][64 + ty * 4];
            ulonglong2 bq0 = *(const ulonglong2*)&Bs[kk][tx * 4];
            ulonglong2 bq1 = *(const ulonglong2*)&Bs[kk][64 + tx * 4];
            unsigned long long b2[4] = {bq0.x, bq0.y, bq1.x, bq1.y};
            float a[8] = {a0.x, a0.y, a0.z, a0.w, a1.x, a1.y, a1.z, a1.w};
            unsigned long long ad[8];
#pragma unroll
            for (int i = 0; i < 8; i++)
                asm("mov.b64 %0, {%1, %1};"
                    : "=l"(ad[i]) : "r"(__float_as_uint(a[i])));
#pragma unroll
            for (int i = 0; i < 8; i++)
#pragma unroll
                for (int j = 0; j < 4; j++)
                    asm("fma.rn.f32x2 %0, %1, %2, %0;"
                        : "+l"(acc2[i][j]) : "l"(ad[i]), "l"(b2[j]));
        }
        __syncthreads();
    }

    float4 bias0 = *(const float4*)(bias + bn + tx * 4);
    float4 bias1 = *(const float4*)(bias + bn + 64 + tx * 4);
#pragma unroll
    for (int i = 0; i < 8; i++) {
        int m = bm + (i < 4 ? ty * 4 + i : 64 + ty * 4 + (i - 4));
        if (m >= NN) continue;
        float2 p0 = u2f2(acc2[i][0]), p1 = u2f2(acc2[i][1]);
        float2 p2 = u2f2(acc2[i][2]), p3 = u2f2(acc2[i][3]);
        float4 o0 = make_float4(p0.x + bias0.x, p0.y + bias0.y,
                                p1.x + bias0.z, p1.y + bias0.w);
        float4 o1 = make_float4(p2.x + bias1.x, p2.y + bias1.y,
                                p3.x + bias1.z, p3.y + bias1.w);
        *(float4*)(g_x0 + (size_t)m * HH + bn + tx * 4) = o0;
        *(float4*)(g_x0 + (size_t)m * HH + bn + 64 + tx * 4) = o1;
    }
}

// ---------------- CSR build ----------------
__global__ void k_zero_deg() {
    int i = blockIdx.x * blockDim.x + threadIdx.x;
    if (i < NN) g_deg[i] = 0;
}
__global__ void k_hist(const int* __restrict__ dst) {
    int e = blockIdx.x * blockDim.x + threadIdx.x;
    if (e < EE) atomicAdd(&g_deg[dst[e]], 1);
}
__global__ __launch_bounds__(1024) void k_scan_local() {
    __shared__ int sh[1024];
    int i = blockIdx.x * 1024 + threadIdx.x;
    int v = (i < NN) ? g_deg[i] : 0;
    sh[threadIdx.x] = v;
    __syncthreads();
#pragma unroll
    for (int o = 1; o < 1024; o <<= 1) {
        int t = (threadIdx.x >= o) ? sh[threadIdx.x - o] : 0;
        __syncthreads();
        sh[threadIdx.x] += t;
        __syncthreads();
    }
    if (i < NN) g_tmp[i] = sh[threadIdx.x];
    if (threadIdx.x == 1023) g_bsum[blockIdx.x] = sh[1023];
}
__global__ void k_scan_bsum(int nb) {
    __shared__ int sh[64];
    int i = threadIdx.x;
    sh[i] = (i < nb) ? g_bsum[i] : 0;
    __syncthreads();
#pragma unroll
    for (int o = 1; o < 64; o <<= 1) {
        int t = (i >= o) ? sh[i - o] : 0;
        __syncthreads();
        sh[i] += t;
        __syncthreads();
    }
    if (i < nb) g_bsum[i] = sh[i];
}
__global__ void k_scan_add() {
    int i = blockIdx.x * blockDim.x + threadIdx.x;
    if (i < NN) {
        int b = i >> 10;
        int incl = g_tmp[i] + (b > 0 ? g_bsum[b - 1] : 0);
        g_rowptr[i + 1] = incl;
        g_cursor[i] = incl - g_deg[i];
        if (i == 0) g_rowptr[0] = 0;
    }
}
__global__ void k_scatter(const int* __restrict__ src, const int* __restrict__ dst) {
    int e = blockIdx.x * blockDim.x + threadIdx.x;
    if (e < EE) {
        int pos = atomicAdd(&g_cursor[dst[e]], 1);
        g_csr_src[pos] = src[e];
    }
}

// ---------------- initial gates ----------------
__global__ __launch_bounds__(256) void k_prep(const float* __restrict__ attl,
                                              const float* __restrict__ attr) {
    int w = (blockIdx.x * blockDim.x + threadIdx.x) >> 5;
    if (w >= NN) return;
    int lane = threadIdx.x & 31;
    const float4* xr = (const float4*)(g_x0 + (size_t)w * HH);
    float4 v0 = xr[lane], v1 = xr[lane + 32];
    const float4* wl = (const float4*)attl;
    const float4* wr = (const float4*)attr;
    float sl = dot4(v0, wl[lane]) + dot4(v1, wl[lane + 32]);
    float sr = dot4(v0, wr[lane]) + dot4(v1, wr[lane + 32]);
    sl = warp_sum(sl);
    sr = warp_sum(sr);
    if (lane == 0) { g_al[0][w] = sl; g_ar[0][w] = sr; }
}

// ---------------- fused layer: inline gates, R3 lane mapping (R11-proven) ---
template <int LIDX, bool LAST>
__global__ __launch_bounds__(256) void k_layer(
    const float* __restrict__ lng, const float* __restrict__ lnb,
    const float* __restrict__ attl, const float* __restrict__ attr,
    const float* __restrict__ Wl, const float* __restrict__ bl,
    float* __restrict__ emb_out, float* __restrict__ logp_out) {
    int d = (blockIdx.x * blockDim.x + threadIdx.x) >> 5;
    if (d >= NN) return;
    int lane = threadIdx.x & 31;

    const float* xin = (LIDX == 0) ? g_x0 : ((LIDX == 2) ? g_xb : g_xa);
    float* xout = (LIDX == 1) ? g_xb : g_xa;
    constexpr int SLOT_IN = (LIDX & 1);
    constexpr int SLOT_OUT = 1 - SLOT_IN;

    const float* alv = g_al[SLOT_IN];
    float ard = g_ar[SLOT_IN][d];
    float aself = 0.5f * tanhf(alv[d] + ard);

    const float4* xd = (const float4*)(xin + (size_t)d * HH);
    float4 v0 = xd[lane], v1 = xd[lane + 32];
    float4 acc0 = make_float4(aself * v0.x, aself * v0.y, aself * v0.z, aself * v0.w);
    float4 acc1 = make_float4(aself * v1.x, aself * v1.y, aself * v1.z, aself * v1.w);

    int beg = g_rowptr[d], end = g_rowptr[d + 1];
    for (int base = beg; base < end; base += 32) {
        int idx = base + lane;
        int s = 0;
        float g = 0.f;
        if (idx < end) {
            s = g_csr_src[idx];
            g = 0.5f * tanhf(alv[s] + ard);
        }
        int cnt = min(32, end - base);
#pragma unroll 4
        for (int j = 0; j < cnt; j++) {
            int sj = __shfl_sync(0xffffffffu, s, j);
            float gj = __shfl_sync(0xffffffffu, g, j);
            const float4* xr = (const float4*)(xin + (size_t)sj * HH);
            float4 u0 = xr[lane], u1 = xr[lane + 32];
            acc0.x = fmaf(gj, u0.x, acc0.x); acc0.y = fmaf(gj, u0.y, acc0.y);
            acc0.z = fmaf(gj, u0.z, acc0.z); acc0.w = fmaf(gj, u0.w, acc0.w);
            acc1.x = fmaf(gj, u1.x, acc1.x); acc1.y = fmaf(gj, u1.y, acc1.y);
            acc1.z = fmaf(gj, u1.z, acc1.z); acc1.w = fmaf(gj, u1.w, acc1.w);
        }
    }

    const float4* x0r = (const float4*)(g_x0 + (size_t)d * HH);
    float4 z0 = x0r[lane], z1 = x0r[lane + 32];
    acc0.x = fmaf(0.1f, z0.x, acc0.x); acc0.y = fmaf(0.1f, z0.y, acc0.y);
    acc0.z = fmaf(0.1f, z0.z, acc0.z); acc0.w = fmaf(0.1f, z0.w, acc0.w);
    acc1.x = fmaf(0.1f, z1.x, acc1.x); acc1.y = fmaf(0.1f, z1.y, acc1.y);
    acc1.z = fmaf(0.1f, z1.z, acc1.z); acc1.w = fmaf(0.1f, z1.w, acc1.w);

    if (!LAST) {
        acc0.x = fmaxf(acc0.x, 0.f); acc0.y = fmaxf(acc0.y, 0.f);
        acc0.z = fmaxf(acc0.z, 0.f); acc0.w = fmaxf(acc0.w, 0.f);
        acc1.x = fmaxf(acc1.x, 0.f); acc1.y = fmaxf(acc1.y, 0.f);
        acc1.z = fmaxf(acc1.z, 0.f); acc1.w = fmaxf(acc1.w, 0.f);
        float sum = acc0.x + acc0.y + acc0.z + acc0.w + acc1.x + acc1.y + acc1.z + acc1.w;
        float sq = acc0.x * acc0.x + acc0.y * acc0.y + acc0.z * acc0.z + acc0.w * acc0.w +
                   acc1.x * acc1.x + acc1.y * acc1.y + acc1.z * acc1.z + acc1.w * acc1.w;
        sum = warp_sum(sum);
        sq = warp_sum(sq);
        float mu = sum * (1.f / HH);
        float var = sq * (1.f / HH) - mu * mu;
        float inv = rsqrtf(var + 1e-5f);
        const float4* gp = (const float4*)lng;
        const float4* bp = (const float4*)lnb;
        float4 gg0 = gp[lane], gg1 = gp[lane + 32];
        float4 bb0 = bp[lane], bb1 = bp[lane + 32];
        float4 y0 = make_float4((acc0.x - mu) * inv * gg0.x + bb0.x,
                                (acc0.y - mu) * inv * gg0.y + bb0.y,
                                (acc0.z - mu) * inv * gg0.z + bb0.z,
                                (acc0.w - mu) * inv * gg0.w + bb0.w);
        float4 y1 = make_float4((acc1.x - mu) * inv * gg1.x + bb1.x,
                                (acc1.y - mu) * inv * gg1.y + bb1.y,
                                (acc1.z - mu) * inv * gg1.z + bb1.z,
                                (acc1.w - mu) * inv * gg1.w + bb1.w);
        float4* xw = (float4*)(xout + (size_t)d * HH);
        xw[lane] = y0;
        xw[lane + 32] = y1;
        const float4* wl = (const float4*)attl;
        const float4* wr = (const float4*)attr;
        float sl = dot4(y0, wl[lane]) + dot4(y1, wl[lane + 32]);
        float sr = dot4(y0, wr[lane]) + dot4(y1, wr[lane + 32]);
        sl = warp_sum(sl);
        sr = warp_sum(sr);
        if (lane == 0) { g_al[SLOT_OUT][d] = sl; g_ar[SLOT_OUT][d] = sr; }
    } else {
        float e[CC];
#pragma unroll
        for (int c = 0; c < CC; c++) {
            const float4* wr = (const float4*)(Wl + c * HH);
            float p = dot4(acc0, wr[lane]) + dot4(acc1, wr[lane + 32]);
            e[c] = warp_sum(p);
        }
        if (lane == 0) {
            float val[CC];
            float m = -1e30f;
#pragma unroll
            for (int c = 0; c < CC; c++) {
                val[c] = e[c] + bl[c];
                m = fmaxf(m, val[c]);
            }
            float ssum = 0.f;
#pragma unroll
            for (int c = 0; c < CC; c++) ssum += expf(val[c] - m);
            float lse = m + logf(ssum);
#pragma unroll
            for (int c = 0; c < CC; c++) {
                if (emb_out) emb_out[(size_t)d * CC + c] = val[c];
                logp_out[(size_t)d * CC + c] = val[c] - lse;
            }
        }
    }
}

extern "C" void kernel_launch(void* const* d_in, const int* in_sizes, int n_in,
                              void* d_out, int out_size) {
    const float* x_in = (const float*)d_in[0];
    const int* ei     = (const int*)d_in[1];
    const float* Wi   = (const float*)d_in[2];
    const float* bi   = (const float*)d_in[3];
    const float* attl = (const float*)d_in[4];
    const float* attr = (const float*)d_in[5];
    const float* lng  = (const float*)d_in[6];
    const float* lnb  = (const float*)d_in[7];
    const float* Wl   = (const float*)d_in[8];
    const float* bl   = (const float*)d_in[9];
    float* out = (float*)d_out;

    const int* src = ei;
    const int* dst = ei + EE;

    // Side stream + events for fork/join (host-side resources; created per call
    // — kernel_launch only runs twice: correctness + capture).
    cudaStream_t side;
    cudaStreamCreateWithFlags(&side, cudaStreamNonBlocking);
    cudaEvent_t evFork, evJoin;
    cudaEventCreateWithFlags(&evFork, cudaEventDisableTiming);
    cudaEventCreateWithFlags(&evJoin, cudaEventDisableTiming);

    // Fork: CSR build on side stream, GEMM chain on main (default) stream.
    cudaEventRecord(evFork, 0);
    cudaStreamWaitEvent(side, evFork, 0);

    k_zero_deg<<<(NN + 255) / 256, 256, 0, side>>>();
    k_hist<<<(EE + 255) / 256, 256, 0, side>>>(dst);
    int nb = (NN + 1023) / 1024;
    k_scan_local<<<nb, 1024, 0, side>>>();
    k_scan_bsum<<<1, 64, 0, side>>>(nb);
    k_scan_add<<<(NN + 255) / 256, 256, 0, side>>>();
    k_scatter<<<(EE + 255) / 256, 256, 0, side>>>(src, dst);
    cudaEventRecord(evJoin, side);

    // Main stream: transpose -> GEMM -> prep (independent of CSR)
    k_transpose<<<(DIN * HH + 255) / 256, 256>>>(Wi);
    dim3 gg((NN + 127) / 128, HH / 128);
    k_gemm<<<gg, 256>>>(x_in, bi);

    int nodeBlocks = (NN + 7) / 8;
    k_prep<<<nodeBlocks, 256>>>(attl, attr);

    // Join before layers (they need rowptr/csr_src AND x0/gates)
    cudaStreamWaitEvent(0, evJoin, 0);

    float* embp = nullptr;
    float* logp = out;
    if (out_size >= 2 * NN * CC) {
        embp = out;
        logp = out + (size_t)NN * CC;
    }

    k_layer<0, false><<<nodeBlocks, 256>>>(lng + 0 * HH, lnb + 0 * HH,
                                           attl + 1 * HH, attr + 1 * HH,
                                           nullptr, nullptr, nullptr, nullptr);
    k_layer<1, false><<<nodeBlocks, 256>>>(lng + 1 * HH, lnb + 1 * HH,
                                           attl + 2 * HH, attr + 2 * HH,
                                           nullptr, nullptr, nullptr, nullptr);
    k_layer<2, false><<<nodeBlocks, 256>>>(lng + 2 * HH, lnb + 2 * HH,
                                           attl + 3 * HH, attr + 3 * HH,
                                           nullptr, nullptr, nullptr, nullptr);
    k_layer<3, true><<<nodeBlocks, 256>>>(nullptr, nullptr, nullptr, nullptr,
                                          Wl, bl, embp, logp);
}